// round 4
// baseline (speedup 1.0000x reference)
#include <cuda_runtime.h>

// Problem constants (fixed by dataset; code handles N <= MAXN)
#define MAXN 100352
#define MAXN2 (2 * MAXN)
#define MAXE 5000192
#define SCAN_TILE 4096
#define PBLOCKS 148
#define PTHREADS 1024
#define SMEM_FLOATS 50176            // >= HALF = ceil(N/2)
#define SMEM_BYTES (SMEM_FLOATS * 4) // 200704 B dynamic smem

// ---- scratch (static device globals; no allocation allowed) ----
__device__ int   g_count2[MAXN2];
__device__ int   g_rowptr2[MAXN2 + 1];
__device__ int   g_cursor2[MAXN2];
__device__ int   g_col[MAXE];
__device__ float g_dinv[MAXN];
__device__ float g_z0[MAXN];
__device__ float g_z[MAXN];
__device__ float g_y[MAXN];
__device__ float g_plo[MAXN], g_phi[MAXN];
__device__ int   g_tilesum[64];
__device__ int   g_is64;
__device__ unsigned int g_bar;

// ---------------------------------------------------------------
// 0) zero virtual-row counters + barrier + detect edge dtype
__global__ void zero_detect_kernel(const unsigned int* e, int N2) {
    int i = blockIdx.x * blockDim.x + threadIdx.x;
    if (i < N2) g_count2[i] = 0;
    if (blockIdx.x == 0 && threadIdx.x == 0) {
        g_bar = 0u;
        int is64 = 1;
        #pragma unroll 1
        for (int k = 1; k < 1024; k += 2) {
            if (e[k] != 0u) { is64 = 0; break; }
        }
        g_is64 = is64;
    }
}

__device__ __forceinline__ int load_idx(const void* eidx, long long pos) {
    if (g_is64) return (int)((const long long*)eidx)[pos];
    return ((const int*)eidx)[pos];
}

// 1) histogram over virtual rows: vr = 2*dst + (src >= HALF)
__global__ void hist_kernel(const void* eidx, int E, int HALF) {
    int e = blockIdx.x * blockDim.x + threadIdx.x;
    if (e >= E) return;
    int s = load_idx(eidx, e);
    int d = load_idx(eidx, (long long)E + e);
    atomicAdd(&g_count2[2 * d + (s >= HALF)], 1);
}

// ---------------- multi-block exclusive scan over 2N counters ----------------
__global__ void scanA_kernel(int N2) {
    __shared__ int wsum[32];
    int t = threadIdx.x;
    int base = blockIdx.x * SCAN_TILE + t * 4;
    int s = 0;
    #pragma unroll
    for (int j = 0; j < 4; j++) {
        int i = base + j;
        if (i < N2) s += g_count2[i];
    }
    #pragma unroll
    for (int o = 16; o; o >>= 1) s += __shfl_xor_sync(0xffffffffu, s, o);
    if ((t & 31) == 0) wsum[t >> 5] = s;
    __syncthreads();
    if (t < 32) {
        int v = wsum[t];
        #pragma unroll
        for (int o = 16; o; o >>= 1) v += __shfl_xor_sync(0xffffffffu, v, o);
        if (t == 0) g_tilesum[blockIdx.x] = v;
    }
}

// exclusive scan -> rowptr2 (+ cursor init, + dinv per node, + rowptr2[N2])
__global__ void scanC_kernel(int N2, int ntiles) {
    __shared__ int wsum[32];
    __shared__ int s_tileoff;
    int t = threadIdx.x;
    int lane = t & 31;
    int warp = t >> 5;

    if (t < 32) {
        int s = 0;
        #pragma unroll
        for (int j = 0; j < 2; j++) {
            int idx = t + j * 32;
            if (idx < ntiles && idx < blockIdx.x) s += g_tilesum[idx];
        }
        #pragma unroll
        for (int o = 16; o; o >>= 1) s += __shfl_xor_sync(0xffffffffu, s, o);
        if (t == 0) s_tileoff = s;
    }

    int base = blockIdx.x * SCAN_TILE + t * 4;   // always even
    int c[4];
    #pragma unroll
    for (int j = 0; j < 4; j++) {
        int i = base + j;
        c[j] = (i < N2) ? g_count2[i] : 0;
    }
    int local = c[0] + c[1] + c[2] + c[3];

    int inc = local;
    #pragma unroll
    for (int o = 1; o < 32; o <<= 1) {
        int v = __shfl_up_sync(0xffffffffu, inc, o);
        if (lane >= o) inc += v;
    }
    if (lane == 31) wsum[warp] = inc;
    __syncthreads();
    if (t < 32) {
        int v = wsum[t];
        int iv = v;
        #pragma unroll
        for (int o = 1; o < 32; o <<= 1) {
            int u = __shfl_up_sync(0xffffffffu, iv, o);
            if (lane >= o) iv += u;
        }
        wsum[t] = iv - v;
    }
    __syncthreads();
    int off = s_tileoff + wsum[warp] + (inc - local);
    #pragma unroll
    for (int j = 0; j < 4; j++) {
        int i = base + j;
        if (i < N2) {
            g_rowptr2[i] = off;
            g_cursor2[i] = off;
            if (i == N2 - 1) g_rowptr2[N2] = off + c[j];
            off += c[j];
        }
    }
    // dinv per node: pairs (base, base+1), (base+2, base+3)
    int n0 = base >> 1;
    if (base + 1 < N2 || base + 1 == N2 - 0) {}  // no-op
    if (2 * n0 + 1 <= N2 - 1) g_dinv[n0] = rsqrtf((float)(c[0] + c[1]) + 1.0f);
    if (2 * (n0 + 1) + 1 <= N2 - 1) g_dinv[n0 + 1] = rsqrtf((float)(c[2] + c[3]) + 1.0f);
}

// 2) CSR placement into split CSR
__global__ void place_kernel(const void* eidx, int E, int HALF) {
    int e = blockIdx.x * blockDim.x + threadIdx.x;
    if (e >= E) return;
    int s = load_idx(eidx, e);
    int d = load_idx(eidx, (long long)E + e);
    int idx = atomicAdd(&g_cursor2[2 * d + (s >= HALF)], 1);
    g_col[idx] = s;
}

// ---------------- persistent fused kernel ----------------
__device__ __forceinline__ void grid_barrier(unsigned int target) {
    __syncthreads();
    if (threadIdx.x == 0) {
        unsigned int* bar = &g_bar;
        asm volatile("red.release.gpu.add.u32 [%0], 1;" :: "l"(bar) : "memory");
        unsigned int v;
        while (true) {
            asm volatile("ld.acquire.gpu.u32 %0, [%1];" : "=r"(v) : "l"(bar) : "memory");
            if (v >= target) break;
            __nanosleep(32);
        }
    }
    __syncthreads();
}

__global__ void __launch_bounds__(PTHREADS, 1)
appnp_kernel(const float* __restrict__ x,
             const float* __restrict__ W1, const float* __restrict__ b1,
             const float* __restrict__ W2, const float* __restrict__ b2,
             const float* __restrict__ W3, const float* __restrict__ b3,
             float* __restrict__ out, int N, int HALF) {
    extern __shared__ float sy[];                 // HALF floats (<=50176)
    __shared__ float sW2[256], sW1[16], sb1[16], sb2[16], sW3[16];
    int t = threadIdx.x;
    if (t < 256) sW2[t] = W2[t];
    if (t < 16) { sW1[t] = W1[t]; sb1[t] = b1[t]; sb2[t] = b2[t]; sW3[t] = W3[t]; }
    __syncthreads();

    int gtid = blockIdx.x * blockDim.x + t;
    int gsize = gridDim.x * blockDim.x;

    // --- encoder collapsed to scalar ---
    for (int i = gtid; i < N; i += gsize) {
        float xv = __ldg(&x[i]);
        float h1[16];
        #pragma unroll
        for (int j = 0; j < 16; j++) h1[j] = fmaxf(xv * sW1[j] + sb1[j], 0.0f);
        float z = 0.0f;
        #pragma unroll
        for (int j = 0; j < 16; j++) {
            float a = sb2[j];
            #pragma unroll
            for (int kk = 0; kk < 16; kk++) a = fmaf(h1[kk], sW2[kk * 16 + j], a);
            z = fmaf(fmaxf(a, 0.0f), sW3[j], z);
        }
        float di = g_dinv[i];
        g_z0[i] = z;
        g_z[i] = z;
        __stcg(&g_y[i], di * z);
    }

    unsigned int bar_target = gridDim.x;
    grid_barrier(bar_target);

    const int half_ctas = gridDim.x >> 1;         // 74
    const int group = (blockIdx.x >= half_ctas) ? 1 : 0;
    const int cig = blockIdx.x - group * half_ctas;
    const int warps_per_group = half_ctas << 5;   // 2368
    const int gw = (cig << 5) + (t >> 5);
    const int lane = t & 31;
    const int off = group ? HALF : 0;
    const int cnt = group ? (N - HALF) : HALF;    // nodes in my half
    float* pout = group ? g_phi : g_plo;
    float bb = __ldg(&b3[0]);

    #pragma unroll 1
    for (int k = 0; k < 10; k++) {
        // (a) load my half of y into SMEM
        #pragma unroll 1
        for (int i = t; i < cnt; i += PTHREADS) sy[i] = __ldcg(&g_y[off + i]);
        __syncthreads();

        // (b) half-row partial sums via SMEM gathers (warp per row)
        #pragma unroll 1
        for (int row = gw; row < N; row += warps_per_group) {
            int beg = __ldg(&g_rowptr2[2 * row + group]);
            int end = __ldg(&g_rowptr2[2 * row + group + 1]);
            float s = 0.0f;
            #pragma unroll 1
            for (int e = beg + lane; e < end; e += 32)
                s += sy[__ldg(&g_col[e]) - off];
            #pragma unroll
            for (int o = 16; o; o >>= 1) s += __shfl_xor_sync(0xffffffffu, s, o);
            if (lane == 0) __stcg(&pout[row], s);
        }
        bar_target += gridDim.x;
        grid_barrier(bar_target);

        // (c) combine: z' = 0.9*(dinv*(plo+phi) + dinv^2*z) + 0.1*z0
        if (gtid < N) {
            int i = gtid;
            float di = g_dinv[i];
            float s = __ldcg(&g_plo[i]) + __ldcg(&g_phi[i]);
            float zn = fmaf(0.9f, fmaf(di, s, di * di * g_z[i]), 0.1f * g_z0[i]);
            g_z[i] = zn;
            if (k < 9) __stcg(&g_y[i], di * zn);
            else       out[i] = zn + bb;
        }
        if (k < 9) {
            bar_target += gridDim.x;
            grid_barrier(bar_target);
        }
    }
}

extern "C" void kernel_launch(void* const* d_in, const int* in_sizes, int n_in,
                              void* d_out, int out_size) {
    const float* x  = (const float*)d_in[0];
    const void*  ei = d_in[1];
    const float* W1 = (const float*)d_in[2];
    const float* b1 = (const float*)d_in[3];
    const float* W2 = (const float*)d_in[4];
    const float* b2 = (const float*)d_in[5];
    const float* W3 = (const float*)d_in[6];
    const float* b3 = (const float*)d_in[7];
    float* out = (float*)d_out;

    int N = in_sizes[0];          // x is [N,1]
    int E = in_sizes[1] / 2;      // edge_index is [2,E]
    int HALF = (N + 1) / 2;
    int N2 = 2 * N;

    int nb2 = (N2 + 255) / 256;
    int eb = (E + 255) / 256;
    int ntiles = (N2 + SCAN_TILE - 1) / SCAN_TILE;

    static int smem_set = 0;
    if (!smem_set) {
        cudaFuncSetAttribute(appnp_kernel,
                             cudaFuncAttributeMaxDynamicSharedMemorySize, SMEM_BYTES);
        smem_set = 1;
    }

    zero_detect_kernel<<<nb2, 256>>>((const unsigned int*)ei, N2);
    hist_kernel<<<eb, 256>>>(ei, E, HALF);
    scanA_kernel<<<ntiles, 1024>>>(N2);
    scanC_kernel<<<ntiles, 1024>>>(N2, ntiles);
    place_kernel<<<eb, 256>>>(ei, E, HALF);
    appnp_kernel<<<PBLOCKS, PTHREADS, SMEM_BYTES>>>(x, W1, b1, W2, b2, W3, b3,
                                                    out, N, HALF);
}

// round 7
// speedup vs baseline: 1.0483x; 1.0483x over previous
#include <cuda_runtime.h>
#include <cuda_fp16.h>

// Problem constants (fixed by dataset; code handles N <= MAXN)
#define MAXN 100352
#define MAXE 5000192
#define SCAN_TILE 4096
#define PROP_BLOCKS 148
#define PROP_THREADS 1024
#define SMEM_BYTES 200704          // >= MAXN * 2 bytes (fp16 y table)

// ---- scratch (static device globals; no allocation allowed) ----
__device__ int   g_count[MAXN];
__device__ int   g_rowptr[MAXN + 1];
__device__ int   g_cursor[MAXN];
__device__ int   g_col[MAXE];
__device__ float g_dinv[MAXN];
__device__ float g_z0[MAXN];
__device__ float g_z[MAXN];
__device__ __align__(16) __half g_yA[MAXN];
__device__ __align__(16) __half g_yB[MAXN];
__device__ int   g_tilesum[32];
__device__ int   g_is64;

// ---------------------------------------------------------------
// 0) zero counters + detect edge dtype (int64 LE -> odd 32-bit words zero)
__global__ void zero_detect_kernel(const unsigned int* e, int N) {
    int i = blockIdx.x * blockDim.x + threadIdx.x;
    if (i < N) g_count[i] = 0;
    if (blockIdx.x == 0 && threadIdx.x == 0) {
        int is64 = 1;
        #pragma unroll 1
        for (int k = 1; k < 1024; k += 2) {
            if (e[k] != 0u) { is64 = 0; break; }
        }
        g_is64 = is64;
    }
}

__device__ __forceinline__ int load_idx(const void* eidx, long long pos) {
    if (g_is64) return (int)((const long long*)eidx)[pos];
    return ((const int*)eidx)[pos];
}

// 1) in-degree histogram over dst
__global__ void hist_kernel(const void* eidx, int E) {
    int e = blockIdx.x * blockDim.x + threadIdx.x;
    if (e >= E) return;
    int d = load_idx(eidx, (long long)E + e);
    atomicAdd(&g_count[d], 1);
}

// 2) scan pass A: per-tile totals
__global__ void __launch_bounds__(1024, 1) scanA_kernel(int N) {
    __shared__ int wsum[32];
    int t = threadIdx.x;
    int base = blockIdx.x * SCAN_TILE + t * 4;
    int s = 0;
    #pragma unroll
    for (int j = 0; j < 4; j++) {
        int i = base + j;
        if (i < N) s += g_count[i];
    }
    #pragma unroll
    for (int o = 16; o; o >>= 1) s += __shfl_xor_sync(0xffffffffu, s, o);
    if ((t & 31) == 0) wsum[t >> 5] = s;
    __syncthreads();
    if (t < 32) {
        int v = wsum[t];
        #pragma unroll
        for (int o = 16; o; o >>= 1) v += __shfl_xor_sync(0xffffffffu, v, o);
        if (t == 0) g_tilesum[blockIdx.x] = v;
    }
}

// 3) scan pass C + fused encoder.
__global__ void __launch_bounds__(1024, 1)
scanC_enc_kernel(const float* __restrict__ x,
                 const float* __restrict__ W1, const float* __restrict__ b1,
                 const float* __restrict__ W2, const float* __restrict__ b2,
                 const float* __restrict__ W3,
                 int N, int ntiles) {
    __shared__ int wsum[32];
    __shared__ int s_tileoff;
    __shared__ float sW2[256], sW1[16], sb1[16], sb2[16], sW3[16];
    int t = threadIdx.x;
    int lane = t & 31;
    int warp = t >> 5;

    if (t < 256) sW2[t] = W2[t];
    if (t < 16) { sW1[t] = W1[t]; sb1[t] = b1[t]; sb2[t] = b2[t]; sW3[t] = W3[t]; }

    if (t < 32) {
        int s = (t < ntiles && t < blockIdx.x) ? g_tilesum[t] : 0;
        #pragma unroll
        for (int o = 16; o; o >>= 1) s += __shfl_xor_sync(0xffffffffu, s, o);
        if (t == 0) s_tileoff = s;
    }

    int base = blockIdx.x * SCAN_TILE + t * 4;
    int c[4];
    #pragma unroll
    for (int j = 0; j < 4; j++) {
        int i = base + j;
        c[j] = (i < N) ? g_count[i] : 0;
    }
    int local = c[0] + c[1] + c[2] + c[3];

    int inc = local;
    #pragma unroll
    for (int o = 1; o < 32; o <<= 1) {
        int v = __shfl_up_sync(0xffffffffu, inc, o);
        if (lane >= o) inc += v;
    }
    if (lane == 31) wsum[warp] = inc;
    __syncthreads();
    if (t < 32) {
        int v = wsum[t];
        int iv = v;
        #pragma unroll
        for (int o = 1; o < 32; o <<= 1) {
            int u = __shfl_up_sync(0xffffffffu, iv, o);
            if (lane >= o) iv += u;
        }
        wsum[t] = iv - v;
    }
    __syncthreads();
    int off = s_tileoff + wsum[warp] + (inc - local);
    #pragma unroll
    for (int j = 0; j < 4; j++) {
        int i = base + j;
        if (i < N) {
            g_rowptr[i] = off;
            g_cursor[i] = off;
            if (i == N - 1) g_rowptr[N] = off + c[j];
            off += c[j];
        }
    }

    // fused encoder for the same 4 nodes
    #pragma unroll 1
    for (int j = 0; j < 4; j++) {
        int i = base + j;
        if (i >= N) break;
        float di = rsqrtf((float)c[j] + 1.0f);
        g_dinv[i] = di;
        float xv = __ldg(&x[i]);
        float h1[16];
        #pragma unroll
        for (int q = 0; q < 16; q++) h1[q] = fmaxf(xv * sW1[q] + sb1[q], 0.0f);
        float z = 0.0f;
        #pragma unroll
        for (int q = 0; q < 16; q++) {
            float a = sb2[q];
            #pragma unroll
            for (int r = 0; r < 16; r++) a = fmaf(h1[r], sW2[r * 16 + q], a);
            z = fmaf(fmaxf(a, 0.0f), sW3[q], z);
        }
        g_z0[i] = z;
        g_z[i] = z;
        g_yA[i] = __float2half(di * z);
    }
}

// 4) CSR placement (cursor pre-initialized to rowptr)
__global__ void place_kernel(const void* eidx, int E) {
    int e = blockIdx.x * blockDim.x + threadIdx.x;
    if (e >= E) return;
    int s = load_idx(eidx, e);
    int d = load_idx(eidx, (long long)E + e);
    int idx = atomicAdd(&g_cursor[d], 1);
    g_col[idx] = s;
}

// 5) one APPNP iteration: full fp16 y table staged in SMEM, LDS gathers.
//    Ping-pong buffers selected IN DEVICE CODE (host cannot take the address
//    of a __device__ global).
__global__ void __launch_bounds__(PROP_THREADS, 1)
prop_kernel(const float* __restrict__ b3, float* __restrict__ out,
            int k, int N) {
    extern __shared__ __half sy[];
    const __half* __restrict__ yin = (k & 1) ? g_yB : g_yA;
    __half* __restrict__ yout      = (k & 1) ? g_yA : g_yB;
    int t = threadIdx.x;

    // stage full y table into SMEM (vectorized 16B)
    int nvec = (N + 7) >> 3;
    const uint4* src = (const uint4*)yin;
    uint4* dst = (uint4*)sy;
    #pragma unroll 1
    for (int i = t; i < nvec; i += PROP_THREADS) dst[i] = src[i];
    __syncthreads();

    int gw = (blockIdx.x * PROP_THREADS + t) >> 5;
    int lane = t & 31;
    int nwarps = (gridDim.x * PROP_THREADS) >> 5;
    float bb = (k == 9) ? __ldg(&b3[0]) : 0.0f;

    #pragma unroll 1
    for (int row = gw; row < N; row += nwarps) {
        int beg = __ldg(&g_rowptr[row]);
        int end = __ldg(&g_rowptr[row + 1]);
        float s = 0.0f;
        #pragma unroll 1
        for (int e = beg + lane; e < end; e += 32)
            s += __half2float(sy[__ldg(&g_col[e])]);
        #pragma unroll
        for (int o = 16; o; o >>= 1) s += __shfl_xor_sync(0xffffffffu, s, o);
        if (lane == 0) {
            float di = g_dinv[row];
            float zn = fmaf(0.9f, fmaf(di, s, di * di * g_z[row]), 0.1f * g_z0[row]);
            g_z[row] = zn;
            if (k < 9) yout[row] = __float2half(di * zn);
            else       out[row] = zn + bb;
        }
    }
}

extern "C" void kernel_launch(void* const* d_in, const int* in_sizes, int n_in,
                              void* d_out, int out_size) {
    const float* x  = (const float*)d_in[0];
    const void*  ei = d_in[1];
    const float* W1 = (const float*)d_in[2];
    const float* b1 = (const float*)d_in[3];
    const float* W2 = (const float*)d_in[4];
    const float* b2 = (const float*)d_in[5];
    const float* W3 = (const float*)d_in[6];
    const float* b3 = (const float*)d_in[7];
    float* out = (float*)d_out;

    int N = in_sizes[0];          // x is [N,1]
    int E = in_sizes[1] / 2;      // edge_index is [2,E]

    int nb = (N + 255) / 256;
    int eb = (E + 255) / 256;
    int ntiles = (N + SCAN_TILE - 1) / SCAN_TILE;

    cudaFuncSetAttribute(prop_kernel,
                         cudaFuncAttributeMaxDynamicSharedMemorySize, SMEM_BYTES);

    zero_detect_kernel<<<nb, 256>>>((const unsigned int*)ei, N);
    hist_kernel<<<eb, 256>>>(ei, E);
    scanA_kernel<<<ntiles, 1024>>>(N);
    scanC_enc_kernel<<<ntiles, 1024>>>(x, W1, b1, W2, b2, W3, N, ntiles);
    place_kernel<<<eb, 256>>>(ei, E);

    // K = 10 iterations, fp16 y ping-pong selected in device code
    for (int k = 0; k < 10; k++)
        prop_kernel<<<PROP_BLOCKS, PROP_THREADS, SMEM_BYTES>>>(b3, out, k, N);
}

// round 8
// speedup vs baseline: 1.3901x; 1.3259x over previous
#include <cuda_runtime.h>
#include <cuda_fp16.h>

// Problem constants (fixed by dataset; code handles N <= MAXN)
#define MAXN 100352
#define MAXE 5000192
#define SCAN_TILE 4096

// ---- scratch (static device globals; no allocation allowed) ----
__device__ int   g_count[MAXN];
__device__ int   g_rowptr[MAXN + 1];
__device__ int   g_cursor[MAXN];
__device__ int   g_col[MAXE];
__device__ __align__(16) float4 g_nd[MAXN];   // {dinv, z0, z, pad}
__device__ __align__(16) __half g_yA[MAXN];
__device__ __align__(16) __half g_yB[MAXN];
__device__ int   g_tilesum[32];
__device__ int   g_is64;

// ---------------------------------------------------------------
// 0) zero counters + detect edge dtype (int64 LE -> odd 32-bit words zero)
__global__ void zero_detect_kernel(const unsigned int* e, int N) {
    int i = blockIdx.x * blockDim.x + threadIdx.x;
    if (i < N) g_count[i] = 0;
    if (blockIdx.x == 0 && threadIdx.x == 0) {
        int is64 = 1;
        #pragma unroll 1
        for (int k = 1; k < 1024; k += 2) {
            if (e[k] != 0u) { is64 = 0; break; }
        }
        g_is64 = is64;
    }
}

__device__ __forceinline__ int load_idx(const void* eidx, long long pos) {
    if (g_is64) return (int)((const long long*)eidx)[pos];
    return ((const int*)eidx)[pos];
}

// 1) in-degree histogram over dst (reads only the dst half: 40MB)
__global__ void hist_kernel(const void* eidx, int E) {
    int e = blockIdx.x * blockDim.x + threadIdx.x;
    if (e >= E) return;
    int d = load_idx(eidx, (long long)E + e);
    atomicAdd(&g_count[d], 1);
}

// 2) scan pass A: per-tile totals
__global__ void __launch_bounds__(1024, 1) scanA_kernel(int N) {
    __shared__ int wsum[32];
    int t = threadIdx.x;
    int base = blockIdx.x * SCAN_TILE + t * 4;
    int s = 0;
    #pragma unroll
    for (int j = 0; j < 4; j++) {
        int i = base + j;
        if (i < N) s += g_count[i];
    }
    #pragma unroll
    for (int o = 16; o; o >>= 1) s += __shfl_xor_sync(0xffffffffu, s, o);
    if ((t & 31) == 0) wsum[t >> 5] = s;
    __syncthreads();
    if (t < 32) {
        int v = wsum[t];
        #pragma unroll
        for (int o = 16; o; o >>= 1) v += __shfl_xor_sync(0xffffffffu, v, o);
        if (t == 0) g_tilesum[blockIdx.x] = v;
    }
}

// 3) scan pass C (slim): exclusive scan -> rowptr + cursor init
__global__ void __launch_bounds__(1024, 1) scanC_kernel(int N, int ntiles) {
    __shared__ int wsum[32];
    __shared__ int s_tileoff;
    int t = threadIdx.x;
    int lane = t & 31;
    int warp = t >> 5;

    if (t < 32) {
        int s = (t < ntiles && t < blockIdx.x) ? g_tilesum[t] : 0;
        #pragma unroll
        for (int o = 16; o; o >>= 1) s += __shfl_xor_sync(0xffffffffu, s, o);
        if (t == 0) s_tileoff = s;
    }

    int base = blockIdx.x * SCAN_TILE + t * 4;
    int c[4];
    #pragma unroll
    for (int j = 0; j < 4; j++) {
        int i = base + j;
        c[j] = (i < N) ? g_count[i] : 0;
    }
    int local = c[0] + c[1] + c[2] + c[3];

    int inc = local;
    #pragma unroll
    for (int o = 1; o < 32; o <<= 1) {
        int v = __shfl_up_sync(0xffffffffu, inc, o);
        if (lane >= o) inc += v;
    }
    if (lane == 31) wsum[warp] = inc;
    __syncthreads();
    if (t < 32) {
        int v = wsum[t];
        int iv = v;
        #pragma unroll
        for (int o = 1; o < 32; o <<= 1) {
            int u = __shfl_up_sync(0xffffffffu, iv, o);
            if (lane >= o) iv += u;
        }
        wsum[t] = iv - v;
    }
    __syncthreads();
    int off = s_tileoff + wsum[warp] + (inc - local);
    #pragma unroll
    for (int j = 0; j < 4; j++) {
        int i = base + j;
        if (i < N) {
            g_rowptr[i] = off;
            g_cursor[i] = off;
            if (i == N - 1) g_rowptr[N] = off + c[j];
            off += c[j];
        }
    }
}

// 4) CSR placement (cursor pre-initialized to rowptr)
__global__ void place_kernel(const void* eidx, int E) {
    int e = blockIdx.x * blockDim.x + threadIdx.x;
    if (e >= E) return;
    int s = load_idx(eidx, e);
    int d = load_idx(eidx, (long long)E + e);
    int idx = atomicAdd(&g_cursor[d], 1);
    g_col[idx] = s;
}

// 5) encoder: z0 = relu(relu(x*W1+b1)@W2+b2)@W3; nd = {dinv, z0, z0};
//    yA = fp16(dinv * z0)
__global__ void encoder_kernel(const float* __restrict__ x,
                               const float* __restrict__ W1, const float* __restrict__ b1,
                               const float* __restrict__ W2, const float* __restrict__ b2,
                               const float* __restrict__ W3, int N) {
    __shared__ float sW2[256], sW1[16], sb1[16], sb2[16], sW3[16];
    int t = threadIdx.x;
    if (t < 256) sW2[t] = W2[t];
    if (t < 16) { sW1[t] = W1[t]; sb1[t] = b1[t]; sb2[t] = b2[t]; sW3[t] = W3[t]; }
    __syncthreads();
    int i = blockIdx.x * blockDim.x + t;
    if (i >= N) return;
    float xv = __ldg(&x[i]);
    float h1[16];
    #pragma unroll
    for (int q = 0; q < 16; q++) h1[q] = fmaxf(xv * sW1[q] + sb1[q], 0.0f);
    float z = 0.0f;
    #pragma unroll
    for (int q = 0; q < 16; q++) {
        float a = sb2[q];
        #pragma unroll
        for (int r = 0; r < 16; r++) a = fmaf(h1[r], sW2[r * 16 + q], a);
        z = fmaf(fmaxf(a, 0.0f), sW3[q], z);
    }
    float di = rsqrtf((float)g_count[i] + 1.0f);
    g_nd[i] = make_float4(di, z, z, 0.0f);
    g_yA[i] = __float2half(di * z);
}

// 6) one APPNP iteration, warp per row (massive latency hiding).
//    y gathers via __ldg (L1-resident 200KB fp16 table);
//    col streamed via __ldcg (L2-only, keeps L1 for the table).
//    z' = 0.9*(dinv*sum + dinv^2*z) + 0.1*z0
__global__ void __launch_bounds__(256)
prop_kernel(const float* __restrict__ b3, float* __restrict__ out,
            int k, int N) {
    const __half* __restrict__ yin = (k & 1) ? g_yB : g_yA;
    __half* __restrict__ yout      = (k & 1) ? g_yA : g_yB;

    int w = (blockIdx.x * 256 + threadIdx.x) >> 5;
    int lane = threadIdx.x & 31;
    if (w >= N) return;

    int rp = 0;
    if (lane < 2) rp = __ldg(&g_rowptr[w + lane]);
    int beg = __shfl_sync(0xffffffffu, rp, 0);
    int end = __shfl_sync(0xffffffffu, rp, 1);

    float s = 0.0f;
    for (int e = beg + lane; e < end; e += 32)
        s += __half2float(__ldg(&yin[__ldcg(&g_col[e])]));
    #pragma unroll
    for (int o = 16; o; o >>= 1) s += __shfl_xor_sync(0xffffffffu, s, o);

    if (lane == 0) {
        float4 nd = g_nd[w];                  // {dinv, z0, z}
        float di = nd.x;
        float zn = fmaf(0.9f, fmaf(di, s, di * di * nd.z), 0.1f * nd.y);
        g_nd[w].z = zn;
        if (k < 9) yout[w] = __float2half(di * zn);
        else       out[w] = zn + __ldg(&b3[0]);
    }
}

extern "C" void kernel_launch(void* const* d_in, const int* in_sizes, int n_in,
                              void* d_out, int out_size) {
    const float* x  = (const float*)d_in[0];
    const void*  ei = d_in[1];
    const float* W1 = (const float*)d_in[2];
    const float* b1 = (const float*)d_in[3];
    const float* W2 = (const float*)d_in[4];
    const float* b2 = (const float*)d_in[5];
    const float* W3 = (const float*)d_in[6];
    const float* b3 = (const float*)d_in[7];
    float* out = (float*)d_out;

    int N = in_sizes[0];          // x is [N,1]
    int E = in_sizes[1] / 2;      // edge_index is [2,E]

    int nb = (N + 255) / 256;
    int eb = (E + 255) / 256;
    int ntiles = (N + SCAN_TILE - 1) / SCAN_TILE;
    int pb = (N * 32 + 255) / 256;          // warp per row

    zero_detect_kernel<<<nb, 256>>>((const unsigned int*)ei, N);
    hist_kernel<<<eb, 256>>>(ei, E);
    scanA_kernel<<<ntiles, 1024>>>(N);
    scanC_kernel<<<ntiles, 1024>>>(N, ntiles);
    place_kernel<<<eb, 256>>>(ei, E);
    encoder_kernel<<<nb, 256>>>(x, W1, b1, W2, b2, W3, N);

    // K = 10 iterations, fp16 y ping-pong selected in device code
    for (int k = 0; k < 10; k++)
        prop_kernel<<<pb, 256>>>(b3, out, k, N);
}